// round 6
// baseline (speedup 1.0000x reference)
#include <cuda_runtime.h>
#include <cuda_fp16.h>

// Sinkhorn distance, B=4, N=4096, d=64, EPS=1e-3, 100 iterations, STAB=1e-8.
// Strategy:
//   1) softmax rows + ||.||^2
//   2) row-max of arg_ij = min((2*dot - x2_i - y2_j)/eps, 0)   (one dot pass)
//   3) build K~ = exp(arg - m_i) in fp16 (row-scaled), plus K~^T  (second dot pass)
//   4) 100x { u~ = e^m / (e^m * K~ v + stab);  v = 1 / (K~^T u~ + stab) }  -- fp16 GEMVs
//   5) dist = sum u~_i * exp(arg_ij - m_i) * v_j * cost_ij      (third dot pass)
// All scratch in __device__ globals (no allocation). All launches graph-capturable.

#define BATCH 4
#define NN 4096
#define DD 64
#define INV_EPS 1000.0f
#define MAX_ITER 100
#define STAB 1e-8f
#define TI 64
#define TJ 64

static constexpr size_t KELEMS = (size_t)BATCH * NN * NN;

__device__ float g_xf[BATCH * NN * DD];
__device__ float g_yf[BATCH * NN * DD];
__device__ float g_x2[BATCH * NN];
__device__ float g_y2[BATCH * NN];
__device__ float g_m[BATCH * NN];
__device__ __align__(128) __half g_K[KELEMS];   // K~ row-major [b][i][j]
__device__ __align__(128) __half g_KT[KELEMS];  // K~^T        [b][j][i]
__device__ float g_v[BATCH * NN];
__device__ float g_ut[BATCH * NN];              // u~ = u * exp(m)
__device__ float g_part[BATCH * 64 * 64];

// ---------------------------------------------------------------------------
// 1) softmax over last dim (64) + sum of squares. One warp per row.
//    rows [0, B*N) -> x, rows [B*N, 2*B*N) -> y
// ---------------------------------------------------------------------------
__global__ void softmax_kernel(const float* __restrict__ x, const float* __restrict__ y) {
    int row  = blockIdx.x * 8 + (threadIdx.x >> 5);
    int lane = threadIdx.x & 31;
    const float* src;
    float* dst;
    float* s2out;
    int r;
    if (row < BATCH * NN) { src = x; dst = g_xf; s2out = g_x2; r = row; }
    else                  { src = y; dst = g_yf; s2out = g_y2; r = row - BATCH * NN; }
    const float* p = src + (size_t)r * DD;
    float a0 = p[lane], a1 = p[lane + 32];
    float mx = fmaxf(a0, a1);
#pragma unroll
    for (int o = 16; o > 0; o >>= 1) mx = fmaxf(mx, __shfl_xor_sync(0xffffffffu, mx, o));
    float e0 = expf(a0 - mx), e1 = expf(a1 - mx);
    float s = e0 + e1;
#pragma unroll
    for (int o = 16; o > 0; o >>= 1) s += __shfl_xor_sync(0xffffffffu, s, o);
    float p0 = e0 / s, p1 = e1 / s;
    dst[(size_t)r * DD + lane]      = p0;
    dst[(size_t)r * DD + lane + 32] = p1;
    float q = p0 * p0 + p1 * p1;
#pragma unroll
    for (int o = 16; o > 0; o >>= 1) q += __shfl_xor_sync(0xffffffffu, q, o);
    if (lane == 0) s2out[r] = q;
}

// ---------------------------------------------------------------------------
// shared 64x64 tile dot micro-kernel pieces (duplicated in 3 kernels for
// identical accumulation order)
// ---------------------------------------------------------------------------

// 2) row max of arg over all j. grid = B * (N/64) = 256 blocks, 256 threads.
__global__ void rowmax_kernel() {
    int b  = blockIdx.x >> 6;
    int ib = (blockIdx.x & 63) << 6;
    __shared__ float xs[TI][DD];
    __shared__ float ys[TJ][DD + 1];
    __shared__ float x2s[TI], y2s[TJ];
    __shared__ float red[TI][17];
    int tid = threadIdx.x;
    for (int t = tid; t < TI * DD; t += 256)
        xs[t >> 6][t & 63] = g_xf[(size_t)(b * NN + ib + (t >> 6)) * DD + (t & 63)];
    if (tid < TI) x2s[tid] = g_x2[b * NN + ib + tid];
    int ty = tid >> 4, tx = tid & 15;
    float mymax[4] = {-1e30f, -1e30f, -1e30f, -1e30f};
    for (int jb = 0; jb < NN; jb += TJ) {
        __syncthreads();
        for (int t = tid; t < TJ * DD; t += 256)
            ys[t >> 6][t & 63] = g_yf[(size_t)(b * NN + jb + (t >> 6)) * DD + (t & 63)];
        if (tid < TJ) y2s[tid] = g_y2[b * NN + jb + tid];
        __syncthreads();
        float acc[4][4] = {};
#pragma unroll 16
        for (int k = 0; k < DD; ++k) {
            float a[4], bb[4];
#pragma unroll
            for (int r = 0; r < 4; ++r) a[r] = xs[ty * 4 + r][k];
#pragma unroll
            for (int c = 0; c < 4; ++c) bb[c] = ys[tx * 4 + c][k];
#pragma unroll
            for (int r = 0; r < 4; ++r)
#pragma unroll
                for (int c = 0; c < 4; ++c) acc[r][c] = fmaf(a[r], bb[c], acc[r][c]);
        }
#pragma unroll
        for (int r = 0; r < 4; ++r) {
            float x2 = x2s[ty * 4 + r];
#pragma unroll
            for (int c = 0; c < 4; ++c) {
                float arg = fminf((2.0f * acc[r][c] - x2 - y2s[tx * 4 + c]) * INV_EPS, 0.0f);
                mymax[r] = fmaxf(mymax[r], arg);
            }
        }
    }
    __syncthreads();
#pragma unroll
    for (int r = 0; r < 4; ++r) red[ty * 4 + r][tx] = mymax[r];
    __syncthreads();
    if (tid < TI) {
        float m = -1e30f;
#pragma unroll
        for (int t = 0; t < 16; ++t) m = fmaxf(m, red[tid][t]);
        g_m[b * NN + ib + tid] = m;
    }
}

// 3) build K~ fp16 (and transposed copy). grid = B * 64 * 64 = 16384 blocks.
__global__ void build_kernel() {
    int b   = blockIdx.x >> 12;
    int rem = blockIdx.x & 4095;
    int ib  = (rem >> 6) << 6;
    int jb  = (rem & 63) << 6;
    __shared__ float xs[TI][DD];
    __shared__ float ys[TJ][DD + 1];
    __shared__ float x2s[TI], y2s[TJ], ms[TI];
    __shared__ __half kts[TJ][TI + 8];
    int tid = threadIdx.x;
    for (int t = tid; t < TI * DD; t += 256)
        xs[t >> 6][t & 63] = g_xf[(size_t)(b * NN + ib + (t >> 6)) * DD + (t & 63)];
    for (int t = tid; t < TJ * DD; t += 256)
        ys[t >> 6][t & 63] = g_yf[(size_t)(b * NN + jb + (t >> 6)) * DD + (t & 63)];
    if (tid < TI) { x2s[tid] = g_x2[b * NN + ib + tid]; ms[tid] = g_m[b * NN + ib + tid]; }
    if (tid >= 64 && tid < 64 + TJ) y2s[tid - 64] = g_y2[b * NN + jb + tid - 64];
    __syncthreads();
    int ty = tid >> 4, tx = tid & 15;
    float acc[4][4] = {};
#pragma unroll 16
    for (int k = 0; k < DD; ++k) {
        float a[4], bb[4];
#pragma unroll
        for (int r = 0; r < 4; ++r) a[r] = xs[ty * 4 + r][k];
#pragma unroll
        for (int c = 0; c < 4; ++c) bb[c] = ys[tx * 4 + c][k];
#pragma unroll
        for (int r = 0; r < 4; ++r)
#pragma unroll
            for (int c = 0; c < 4; ++c) acc[r][c] = fmaf(a[r], bb[c], acc[r][c]);
    }
#pragma unroll
    for (int r = 0; r < 4; ++r) {
        int i = ty * 4 + r;
        float x2 = x2s[i];
        float m  = ms[i];
        __half hv[4];
#pragma unroll
        for (int c = 0; c < 4; ++c) {
            int j = tx * 4 + c;
            float arg = fminf((2.0f * acc[r][c] - x2 - y2s[j]) * INV_EPS, 0.0f);
            float kv  = __expf(arg - m);
            hv[c] = __float2half_rn(kv);
            kts[j][i] = hv[c];
        }
        size_t rowo = (size_t)(b * NN + ib + i) * NN + jb + tx * 4;
        __half2* dst = reinterpret_cast<__half2*>(&g_K[rowo]);
        dst[0] = __halves2half2(hv[0], hv[1]);
        dst[1] = __halves2half2(hv[2], hv[3]);
    }
    __syncthreads();
    for (int t = tid; t < TJ * TI; t += 256) {
        int j = t >> 6, i = t & 63;
        g_KT[(size_t)(b * NN + jb + j) * NN + ib + i] = kts[j][i];
    }
}

__global__ void init_v_kernel() {
    int i = blockIdx.x * 256 + threadIdx.x;
    if (i < BATCH * NN) g_v[i] = 1.0f / NN;
}

// 4a) u~ = e^m / (e^m * (K~ v) + stab). grid = B*N/16 = 1024 blocks, 256 thr.
__global__ void matvec_u_kernel() {
    __shared__ __align__(16) float sv[NN];
    int b  = blockIdx.x >> 8;
    int rb = (blockIdx.x & 255) << 4;
    for (int t = threadIdx.x; t < NN; t += 256) sv[t] = g_v[b * NN + t];
    __syncthreads();
    int warp = threadIdx.x >> 5, lane = threadIdx.x & 31;
    const float4* sv4 = reinterpret_cast<const float4*>(sv);
    for (int rr = warp; rr < 16; rr += 8) {
        int i = rb + rr;
        const float4* kr = reinterpret_cast<const float4*>(g_K + (size_t)(b * NN + i) * NN);
        float s = 0.0f;
#pragma unroll 4
        for (int c = lane; c < NN / 8; c += 32) {
            float4 kk = __ldcs(kr + c);
            const __half2* hh = reinterpret_cast<const __half2*>(&kk);
            float4 v0 = sv4[2 * c], v1 = sv4[2 * c + 1];
            float2 f0 = __half22float2(hh[0]);
            float2 f1 = __half22float2(hh[1]);
            float2 f2 = __half22float2(hh[2]);
            float2 f3 = __half22float2(hh[3]);
            s = fmaf(f0.x, v0.x, s); s = fmaf(f0.y, v0.y, s);
            s = fmaf(f1.x, v0.z, s); s = fmaf(f1.y, v0.w, s);
            s = fmaf(f2.x, v1.x, s); s = fmaf(f2.y, v1.y, s);
            s = fmaf(f3.x, v1.z, s); s = fmaf(f3.y, v1.w, s);
        }
#pragma unroll
        for (int o = 16; o > 0; o >>= 1) s += __shfl_xor_sync(0xffffffffu, s, o);
        if (lane == 0) {
            float em = expf(g_m[b * NN + i]);
            float u  = 1.0f / (em * s + STAB);
            g_ut[b * NN + i] = u * em;
        }
    }
}

// 4b) v = 1 / (K~^T u~ + stab)
__global__ void matvec_v_kernel() {
    __shared__ __align__(16) float sv[NN];
    int b  = blockIdx.x >> 8;
    int rb = (blockIdx.x & 255) << 4;
    for (int t = threadIdx.x; t < NN; t += 256) sv[t] = g_ut[b * NN + t];
    __syncthreads();
    int warp = threadIdx.x >> 5, lane = threadIdx.x & 31;
    const float4* sv4 = reinterpret_cast<const float4*>(sv);
    for (int rr = warp; rr < 16; rr += 8) {
        int j = rb + rr;
        const float4* kr = reinterpret_cast<const float4*>(g_KT + (size_t)(b * NN + j) * NN);
        float s = 0.0f;
#pragma unroll 4
        for (int c = lane; c < NN / 8; c += 32) {
            float4 kk = __ldcs(kr + c);
            const __half2* hh = reinterpret_cast<const __half2*>(&kk);
            float4 v0 = sv4[2 * c], v1 = sv4[2 * c + 1];
            float2 f0 = __half22float2(hh[0]);
            float2 f1 = __half22float2(hh[1]);
            float2 f2 = __half22float2(hh[2]);
            float2 f3 = __half22float2(hh[3]);
            s = fmaf(f0.x, v0.x, s); s = fmaf(f0.y, v0.y, s);
            s = fmaf(f1.x, v0.z, s); s = fmaf(f1.y, v0.w, s);
            s = fmaf(f2.x, v1.x, s); s = fmaf(f2.y, v1.y, s);
            s = fmaf(f3.x, v1.z, s); s = fmaf(f3.y, v1.w, s);
        }
#pragma unroll
        for (int o = 16; o > 0; o >>= 1) s += __shfl_xor_sync(0xffffffffu, s, o);
        if (lane == 0) g_v[b * NN + j] = 1.0f / (s + STAB);
    }
}

// 5) dist partial sums: sum_ij  u~_i * exp(arg_ij - m_i) * v_j * cost_ij
__global__ void final_kernel() {
    int b   = blockIdx.x >> 12;
    int rem = blockIdx.x & 4095;
    int ib  = (rem >> 6) << 6;
    int jb  = (rem & 63) << 6;
    __shared__ float xs[TI][DD];
    __shared__ float ys[TJ][DD + 1];
    __shared__ float x2s[TI], y2s[TJ], ms[TI], uts[TI], vs[TJ];
    __shared__ float redsum[256];
    int tid = threadIdx.x;
    for (int t = tid; t < TI * DD; t += 256)
        xs[t >> 6][t & 63] = g_xf[(size_t)(b * NN + ib + (t >> 6)) * DD + (t & 63)];
    for (int t = tid; t < TJ * DD; t += 256)
        ys[t >> 6][t & 63] = g_yf[(size_t)(b * NN + jb + (t >> 6)) * DD + (t & 63)];
    if (tid < TI) {
        x2s[tid] = g_x2[b * NN + ib + tid];
        ms[tid]  = g_m[b * NN + ib + tid];
        uts[tid] = g_ut[b * NN + ib + tid];
    }
    if (tid >= 64 && tid < 64 + TJ) {
        y2s[tid - 64] = g_y2[b * NN + jb + tid - 64];
        vs[tid - 64]  = g_v[b * NN + jb + tid - 64];
    }
    __syncthreads();
    int ty = tid >> 4, tx = tid & 15;
    float acc[4][4] = {};
#pragma unroll 16
    for (int k = 0; k < DD; ++k) {
        float a[4], bb[4];
#pragma unroll
        for (int r = 0; r < 4; ++r) a[r] = xs[ty * 4 + r][k];
#pragma unroll
        for (int c = 0; c < 4; ++c) bb[c] = ys[tx * 4 + c][k];
#pragma unroll
        for (int r = 0; r < 4; ++r)
#pragma unroll
            for (int c = 0; c < 4; ++c) acc[r][c] = fmaf(a[r], bb[c], acc[r][c]);
    }
    float tsum = 0.0f;
#pragma unroll
    for (int r = 0; r < 4; ++r) {
        int i = ty * 4 + r;
        float x2 = x2s[i], m = ms[i], ut = uts[i];
#pragma unroll
        for (int c = 0; c < 4; ++c) {
            int j = tx * 4 + c;
            float cost = fmaxf(x2 + y2s[j] - 2.0f * acc[r][c], 0.0f);
            float kk   = __expf(-cost * INV_EPS - m);
            tsum = fmaf(ut * kk, vs[j] * cost, tsum);
        }
    }
    redsum[tid] = tsum;
    __syncthreads();
#pragma unroll
    for (int o = 128; o > 0; o >>= 1) {
        if (tid < o) redsum[tid] += redsum[tid + o];
        __syncthreads();
    }
    if (tid == 0) g_part[blockIdx.x] = redsum[0];
}

__global__ void reduce_kernel(float* __restrict__ out) {
    __shared__ float sh[256];
    float s = 0.0f;
    for (int t = threadIdx.x; t < BATCH * 64 * 64; t += 256) s += g_part[t];
    sh[threadIdx.x] = s;
    __syncthreads();
#pragma unroll
    for (int o = 128; o > 0; o >>= 1) {
        if (threadIdx.x < o) sh[threadIdx.x] += sh[threadIdx.x + o];
        __syncthreads();
    }
    if (threadIdx.x == 0) out[0] = sh[0];
}

extern "C" void kernel_launch(void* const* d_in, const int* in_sizes, int n_in,
                              void* d_out, int out_size) {
    const float* x = (const float*)d_in[0];
    const float* y = (const float*)d_in[1];
    float* out = (float*)d_out;

    softmax_kernel<<<(2 * BATCH * NN) / 8, 256>>>(x, y);
    rowmax_kernel<<<BATCH * (NN / 64), 256>>>();
    build_kernel<<<BATCH * 64 * 64, 256>>>();
    init_v_kernel<<<(BATCH * NN + 255) / 256, 256>>>();
    for (int it = 0; it < MAX_ITER; ++it) {
        matvec_u_kernel<<<BATCH * (NN / 16), 256>>>();
        matvec_v_kernel<<<BATCH * (NN / 16), 256>>>();
    }
    final_kernel<<<BATCH * 64 * 64, 256>>>();
    reduce_kernel<<<1, 256>>>(out);
}

// round 7
// speedup vs baseline: 1.0055x; 1.0055x over previous
#include <cuda_runtime.h>
#include <cuda_fp16.h>

// Sinkhorn distance, B=4, N=4096, d=64, EPS=1e-3, 100 iterations, STAB=1e-8.
// Strategy:
//   1) softmax rows + ||.||^2
//   2) row-max of arg_ij = min((2*dot - x2_i - y2_j)/eps, 0)   (one dot pass)
//   3) build K~ = exp(arg - m_i) in fp16 (row-scaled), plus K~^T  (second dot pass)
//   4) 100x { u~ = e^m / (e^m * K~ v + stab);  v = 1 / (K~^T u~ + stab) }  -- fp16 GEMVs
//   5) dist = sum u~_i * exp(arg_ij - m_i) * v_j * cost_ij      (third dot pass)
// All scratch in __device__ globals (no allocation). All launches graph-capturable.

#define BATCH 4
#define NN 4096
#define DD 64
#define INV_EPS 1000.0f
#define MAX_ITER 100
#define STAB 1e-8f
#define TI 64
#define TJ 64

static constexpr size_t KELEMS = (size_t)BATCH * NN * NN;

__device__ float g_xf[BATCH * NN * DD];
__device__ float g_yf[BATCH * NN * DD];
__device__ float g_x2[BATCH * NN];
__device__ float g_y2[BATCH * NN];
__device__ float g_m[BATCH * NN];
__device__ __align__(128) __half g_K[KELEMS];   // K~ row-major [b][i][j]
__device__ __align__(128) __half g_KT[KELEMS];  // K~^T        [b][j][i]
__device__ float g_v[BATCH * NN];
__device__ float g_ut[BATCH * NN];              // u~ = u * exp(m)
__device__ float g_part[BATCH * 64 * 64];

// ---------------------------------------------------------------------------
// 1) softmax over last dim (64) + sum of squares. One warp per row.
//    rows [0, B*N) -> x, rows [B*N, 2*B*N) -> y
// ---------------------------------------------------------------------------
__global__ void softmax_kernel(const float* __restrict__ x, const float* __restrict__ y) {
    int row  = blockIdx.x * 8 + (threadIdx.x >> 5);
    int lane = threadIdx.x & 31;
    const float* src;
    float* dst;
    float* s2out;
    int r;
    if (row < BATCH * NN) { src = x; dst = g_xf; s2out = g_x2; r = row; }
    else                  { src = y; dst = g_yf; s2out = g_y2; r = row - BATCH * NN; }
    const float* p = src + (size_t)r * DD;
    float a0 = p[lane], a1 = p[lane + 32];
    float mx = fmaxf(a0, a1);
#pragma unroll
    for (int o = 16; o > 0; o >>= 1) mx = fmaxf(mx, __shfl_xor_sync(0xffffffffu, mx, o));
    float e0 = expf(a0 - mx), e1 = expf(a1 - mx);
    float s = e0 + e1;
#pragma unroll
    for (int o = 16; o > 0; o >>= 1) s += __shfl_xor_sync(0xffffffffu, s, o);
    float p0 = e0 / s, p1 = e1 / s;
    dst[(size_t)r * DD + lane]      = p0;
    dst[(size_t)r * DD + lane + 32] = p1;
    float q = p0 * p0 + p1 * p1;
#pragma unroll
    for (int o = 16; o > 0; o >>= 1) q += __shfl_xor_sync(0xffffffffu, q, o);
    if (lane == 0) s2out[r] = q;
}

// ---------------------------------------------------------------------------
// shared 64x64 tile dot micro-kernel pieces (duplicated in 3 kernels for
// identical accumulation order)
// ---------------------------------------------------------------------------

// 2) row max of arg over all j. grid = B * (N/64) = 256 blocks, 256 threads.
__global__ void rowmax_kernel() {
    int b  = blockIdx.x >> 6;
    int ib = (blockIdx.x & 63) << 6;
    __shared__ float xs[TI][DD];
    __shared__ float ys[TJ][DD + 1];
    __shared__ float x2s[TI], y2s[TJ];
    __shared__ float red[TI][17];
    int tid = threadIdx.x;
    for (int t = tid; t < TI * DD; t += 256)
        xs[t >> 6][t & 63] = g_xf[(size_t)(b * NN + ib + (t >> 6)) * DD + (t & 63)];
    if (tid < TI) x2s[tid] = g_x2[b * NN + ib + tid];
    int ty = tid >> 4, tx = tid & 15;
    float mymax[4] = {-1e30f, -1e30f, -1e30f, -1e30f};
    for (int jb = 0; jb < NN; jb += TJ) {
        __syncthreads();
        for (int t = tid; t < TJ * DD; t += 256)
            ys[t >> 6][t & 63] = g_yf[(size_t)(b * NN + jb + (t >> 6)) * DD + (t & 63)];
        if (tid < TJ) y2s[tid] = g_y2[b * NN + jb + tid];
        __syncthreads();
        float acc[4][4] = {};
#pragma unroll 16
        for (int k = 0; k < DD; ++k) {
            float a[4], bb[4];
#pragma unroll
            for (int r = 0; r < 4; ++r) a[r] = xs[ty * 4 + r][k];
#pragma unroll
            for (int c = 0; c < 4; ++c) bb[c] = ys[tx * 4 + c][k];
#pragma unroll
            for (int r = 0; r < 4; ++r)
#pragma unroll
                for (int c = 0; c < 4; ++c) acc[r][c] = fmaf(a[r], bb[c], acc[r][c]);
        }
#pragma unroll
        for (int r = 0; r < 4; ++r) {
            float x2 = x2s[ty * 4 + r];
#pragma unroll
            for (int c = 0; c < 4; ++c) {
                float arg = fminf((2.0f * acc[r][c] - x2 - y2s[tx * 4 + c]) * INV_EPS, 0.0f);
                mymax[r] = fmaxf(mymax[r], arg);
            }
        }
    }
    __syncthreads();
#pragma unroll
    for (int r = 0; r < 4; ++r) red[ty * 4 + r][tx] = mymax[r];
    __syncthreads();
    if (tid < TI) {
        float m = -1e30f;
#pragma unroll
        for (int t = 0; t < 16; ++t) m = fmaxf(m, red[tid][t]);
        g_m[b * NN + ib + tid] = m;
    }
}

// 3) build K~ fp16 (and transposed copy). grid = B * 64 * 64 = 16384 blocks.
__global__ void build_kernel() {
    int b   = blockIdx.x >> 12;
    int rem = blockIdx.x & 4095;
    int ib  = (rem >> 6) << 6;
    int jb  = (rem & 63) << 6;
    __shared__ float xs[TI][DD];
    __shared__ float ys[TJ][DD + 1];
    __shared__ float x2s[TI], y2s[TJ], ms[TI];
    __shared__ __half kts[TJ][TI + 8];
    int tid = threadIdx.x;
    for (int t = tid; t < TI * DD; t += 256)
        xs[t >> 6][t & 63] = g_xf[(size_t)(b * NN + ib + (t >> 6)) * DD + (t & 63)];
    for (int t = tid; t < TJ * DD; t += 256)
        ys[t >> 6][t & 63] = g_yf[(size_t)(b * NN + jb + (t >> 6)) * DD + (t & 63)];
    if (tid < TI) { x2s[tid] = g_x2[b * NN + ib + tid]; ms[tid] = g_m[b * NN + ib + tid]; }
    if (tid >= 64 && tid < 64 + TJ) y2s[tid - 64] = g_y2[b * NN + jb + tid - 64];
    __syncthreads();
    int ty = tid >> 4, tx = tid & 15;
    float acc[4][4] = {};
#pragma unroll 16
    for (int k = 0; k < DD; ++k) {
        float a[4], bb[4];
#pragma unroll
        for (int r = 0; r < 4; ++r) a[r] = xs[ty * 4 + r][k];
#pragma unroll
        for (int c = 0; c < 4; ++c) bb[c] = ys[tx * 4 + c][k];
#pragma unroll
        for (int r = 0; r < 4; ++r)
#pragma unroll
            for (int c = 0; c < 4; ++c) acc[r][c] = fmaf(a[r], bb[c], acc[r][c]);
    }
#pragma unroll
    for (int r = 0; r < 4; ++r) {
        int i = ty * 4 + r;
        float x2 = x2s[i];
        float m  = ms[i];
        __half hv[4];
#pragma unroll
        for (int c = 0; c < 4; ++c) {
            int j = tx * 4 + c;
            float arg = fminf((2.0f * acc[r][c] - x2 - y2s[j]) * INV_EPS, 0.0f);
            float kv  = __expf(arg - m);
            hv[c] = __float2half_rn(kv);
            kts[j][i] = hv[c];
        }
        size_t rowo = (size_t)(b * NN + ib + i) * NN + jb + tx * 4;
        __half2* dst = reinterpret_cast<__half2*>(&g_K[rowo]);
        dst[0] = __halves2half2(hv[0], hv[1]);
        dst[1] = __halves2half2(hv[2], hv[3]);
    }
    __syncthreads();
    for (int t = tid; t < TJ * TI; t += 256) {
        int j = t >> 6, i = t & 63;
        g_KT[(size_t)(b * NN + jb + j) * NN + ib + i] = kts[j][i];
    }
}

__global__ void init_v_kernel() {
    int i = blockIdx.x * 256 + threadIdx.x;
    if (i < BATCH * NN) g_v[i] = 1.0f / NN;
}

// 4a) u~ = e^m / (e^m * (K~ v) + stab). grid = B*N/16 = 1024 blocks, 256 thr.
__global__ void matvec_u_kernel() {
    __shared__ __align__(16) float sv[NN];
    int b  = blockIdx.x >> 8;
    int rb = (blockIdx.x & 255) << 4;
    for (int t = threadIdx.x; t < NN; t += 256) sv[t] = g_v[b * NN + t];
    __syncthreads();
    int warp = threadIdx.x >> 5, lane = threadIdx.x & 31;
    const float4* sv4 = reinterpret_cast<const float4*>(sv);
    for (int rr = warp; rr < 16; rr += 8) {
        int i = rb + rr;
        const float4* kr = reinterpret_cast<const float4*>(g_K + (size_t)(b * NN + i) * NN);
        float s = 0.0f;
#pragma unroll 4
        for (int c = lane; c < NN / 8; c += 32) {
            float4 kk = __ldcs(kr + c);
            const __half2* hh = reinterpret_cast<const __half2*>(&kk);
            float4 v0 = sv4[2 * c], v1 = sv4[2 * c + 1];
            float2 f0 = __half22float2(hh[0]);
            float2 f1 = __half22float2(hh[1]);
            float2 f2 = __half22float2(hh[2]);
            float2 f3 = __half22float2(hh[3]);
            s = fmaf(f0.x, v0.x, s); s = fmaf(f0.y, v0.y, s);
            s = fmaf(f1.x, v0.z, s); s = fmaf(f1.y, v0.w, s);
            s = fmaf(f2.x, v1.x, s); s = fmaf(f2.y, v1.y, s);
            s = fmaf(f3.x, v1.z, s); s = fmaf(f3.y, v1.w, s);
        }
#pragma unroll
        for (int o = 16; o > 0; o >>= 1) s += __shfl_xor_sync(0xffffffffu, s, o);
        if (lane == 0) {
            float em = expf(g_m[b * NN + i]);
            float u  = 1.0f / (em * s + STAB);
            g_ut[b * NN + i] = u * em;
        }
    }
}

// 4b) v = 1 / (K~^T u~ + stab)
__global__ void matvec_v_kernel() {
    __shared__ __align__(16) float sv[NN];
    int b  = blockIdx.x >> 8;
    int rb = (blockIdx.x & 255) << 4;
    for (int t = threadIdx.x; t < NN; t += 256) sv[t] = g_ut[b * NN + t];
    __syncthreads();
    int warp = threadIdx.x >> 5, lane = threadIdx.x & 31;
    const float4* sv4 = reinterpret_cast<const float4*>(sv);
    for (int rr = warp; rr < 16; rr += 8) {
        int j = rb + rr;
        const float4* kr = reinterpret_cast<const float4*>(g_KT + (size_t)(b * NN + j) * NN);
        float s = 0.0f;
#pragma unroll 4
        for (int c = lane; c < NN / 8; c += 32) {
            float4 kk = __ldcs(kr + c);
            const __half2* hh = reinterpret_cast<const __half2*>(&kk);
            float4 v0 = sv4[2 * c], v1 = sv4[2 * c + 1];
            float2 f0 = __half22float2(hh[0]);
            float2 f1 = __half22float2(hh[1]);
            float2 f2 = __half22float2(hh[2]);
            float2 f3 = __half22float2(hh[3]);
            s = fmaf(f0.x, v0.x, s); s = fmaf(f0.y, v0.y, s);
            s = fmaf(f1.x, v0.z, s); s = fmaf(f1.y, v0.w, s);
            s = fmaf(f2.x, v1.x, s); s = fmaf(f2.y, v1.y, s);
            s = fmaf(f3.x, v1.z, s); s = fmaf(f3.y, v1.w, s);
        }
#pragma unroll
        for (int o = 16; o > 0; o >>= 1) s += __shfl_xor_sync(0xffffffffu, s, o);
        if (lane == 0) g_v[b * NN + j] = 1.0f / (s + STAB);
    }
}

// 5) dist partial sums: sum_ij  u~_i * exp(arg_ij - m_i) * v_j * cost_ij
__global__ void final_kernel() {
    int b   = blockIdx.x >> 12;
    int rem = blockIdx.x & 4095;
    int ib  = (rem >> 6) << 6;
    int jb  = (rem & 63) << 6;
    __shared__ float xs[TI][DD];
    __shared__ float ys[TJ][DD + 1];
    __shared__ float x2s[TI], y2s[TJ], ms[TI], uts[TI], vs[TJ];
    __shared__ float redsum[256];
    int tid = threadIdx.x;
    for (int t = tid; t < TI * DD; t += 256)
        xs[t >> 6][t & 63] = g_xf[(size_t)(b * NN + ib + (t >> 6)) * DD + (t & 63)];
    for (int t = tid; t < TJ * DD; t += 256)
        ys[t >> 6][t & 63] = g_yf[(size_t)(b * NN + jb + (t >> 6)) * DD + (t & 63)];
    if (tid < TI) {
        x2s[tid] = g_x2[b * NN + ib + tid];
        ms[tid]  = g_m[b * NN + ib + tid];
        uts[tid] = g_ut[b * NN + ib + tid];
    }
    if (tid >= 64 && tid < 64 + TJ) {
        y2s[tid - 64] = g_y2[b * NN + jb + tid - 64];
        vs[tid - 64]  = g_v[b * NN + jb + tid - 64];
    }
    __syncthreads();
    int ty = tid >> 4, tx = tid & 15;
    float acc[4][4] = {};
#pragma unroll 16
    for (int k = 0; k < DD; ++k) {
        float a[4], bb[4];
#pragma unroll
        for (int r = 0; r < 4; ++r) a[r] = xs[ty * 4 + r][k];
#pragma unroll
        for (int c = 0; c < 4; ++c) bb[c] = ys[tx * 4 + c][k];
#pragma unroll
        for (int r = 0; r < 4; ++r)
#pragma unroll
            for (int c = 0; c < 4; ++c) acc[r][c] = fmaf(a[r], bb[c], acc[r][c]);
    }
    float tsum = 0.0f;
#pragma unroll
    for (int r = 0; r < 4; ++r) {
        int i = ty * 4 + r;
        float x2 = x2s[i], m = ms[i], ut = uts[i];
#pragma unroll
        for (int c = 0; c < 4; ++c) {
            int j = tx * 4 + c;
            float cost = fmaxf(x2 + y2s[j] - 2.0f * acc[r][c], 0.0f);
            float kk   = __expf(-cost * INV_EPS - m);
            tsum = fmaf(ut * kk, vs[j] * cost, tsum);
        }
    }
    redsum[tid] = tsum;
    __syncthreads();
#pragma unroll
    for (int o = 128; o > 0; o >>= 1) {
        if (tid < o) redsum[tid] += redsum[tid + o];
        __syncthreads();
    }
    if (tid == 0) g_part[blockIdx.x] = redsum[0];
}

__global__ void reduce_kernel(float* __restrict__ out) {
    __shared__ float sh[256];
    float s = 0.0f;
    for (int t = threadIdx.x; t < BATCH * 64 * 64; t += 256) s += g_part[t];
    sh[threadIdx.x] = s;
    __syncthreads();
#pragma unroll
    for (int o = 128; o > 0; o >>= 1) {
        if (threadIdx.x < o) sh[threadIdx.x] += sh[threadIdx.x + o];
        __syncthreads();
    }
    if (threadIdx.x == 0) out[0] = sh[0];
}

extern "C" void kernel_launch(void* const* d_in, const int* in_sizes, int n_in,
                              void* d_out, int out_size) {
    const float* x = (const float*)d_in[0];
    const float* y = (const float*)d_in[1];
    float* out = (float*)d_out;

    softmax_kernel<<<(2 * BATCH * NN) / 8, 256>>>(x, y);
    rowmax_kernel<<<BATCH * (NN / 64), 256>>>();
    build_kernel<<<BATCH * 64 * 64, 256>>>();
    init_v_kernel<<<(BATCH * NN + 255) / 256, 256>>>();
    for (int it = 0; it < MAX_ITER; ++it) {
        matvec_u_kernel<<<BATCH * (NN / 16), 256>>>();
        matvec_v_kernel<<<BATCH * (NN / 16), 256>>>();
    }
    final_kernel<<<BATCH * 64 * 64, 256>>>();
    reduce_kernel<<<1, 256>>>(out);
}